// round 6
// baseline (speedup 1.0000x reference)
#include <cuda_runtime.h>
#include <cstdint>

#define L_NUM 63

// compact block index: S(l) = number of (layer,dpair) 16-float blocks before layer l
__host__ __device__ __forceinline__ constexpr int S_blk(int l) {
    int m = l >> 1;
    return (l & 1) ? (m + 1) * (m + 1) : m * (m + 1);
}
#define NBLK 1024
#define WT_FLOATS (NBLK * 16)   // 16384 floats = 64 KB

__device__ float  g_Wt[WT_FLOATS];   // staging (prep kernel writes here)
__device__ float2 g_W2p[L_NUM * 8];

// 64KB weight table lives in constant memory (uniform-port broadcast, off the l1tex crossbar)
__constant__ ulonglong2 c_W[NBLK * 4];

// masked / transposed / d-pair-interleaved compact weight table
__global__ void prep_kernel(const float* __restrict__ W1, const float* __restrict__ W2) {
    int i = blockIdx.x * blockDim.x + threadIdx.x;
    if (i < 63 * 32 * 16) {
        int p  = i & 1;
        int h  = (i >> 1) & 7;
        int dp = (i >> 4) & 31;
        int l  = i >> 9;
        if (dp <= (l >> 1)) {
            int d = 2 * dp + p;
            float v = (d <= l) ? W1[l * 504 + h * 63 + d] : 0.0f;
            g_Wt[(S_blk(l) + dp) * 16 + h * 2 + p] = v;
        }
    } else {
        int j = i - 63 * 32 * 16;
        if (j < L_NUM * 8) {
            int l = j >> 3, h = j & 7;
            g_W2p[j] = make_float2(W2[l * 16 + h], W2[l * 16 + 8 + h]);
        }
    }
}

__device__ __forceinline__ unsigned long long fma2(unsigned long long a,
                                                   unsigned long long b,
                                                   unsigned long long c) {
    unsigned long long d;
    asm("fma.rn.f32x2 %0, %1, %2, %3;" : "=l"(d) : "l"(a), "l"(b), "l"(c));
    return d;
}
__device__ __forceinline__ void unpack2(unsigned long long v, float& lo, float& hi) {
    asm("mov.b64 {%0, %1}, %2;" : "=f"(lo), "=f"(hi) : "l"(v));
}
__device__ __forceinline__ unsigned long long dup2(float f) {
    unsigned long long v;
    asm("mov.b64 %0, {%1, %1};" : "=l"(v) : "f"(f));
    return v;
}
__device__ __forceinline__ float tanh_fast(float a) {
    float y; asm("tanh.approx.f32 %0, %1;" : "=f"(y) : "f"(a)); return y;
}
__device__ __forceinline__ float exp_fast(float a) {
    float y; asm("ex2.approx.f32 %0, %1;" : "=f"(y) : "f"(a * 1.442695041f)); return y;
}

#define XZ_STRIDE 66   // floats; row base 8B-aligned (264B), all accesses <=8B granules

__global__ __launch_bounds__(128, 4)
void flow_kernel(const float* __restrict__ x,
                 const float* __restrict__ ipar,
                 const float* __restrict__ b1g,
                 const float* __restrict__ b2g,
                 float* __restrict__ z_out,
                 float* __restrict__ ld_out,
                 int has_ld)
{
    __shared__ float sXZ[128 * XZ_STRIDE];          // 33792 B
    __shared__ float sB1[504];
    __shared__ unsigned long long sW2[504];         // packed (mu,alpha) weights
    __shared__ float sB2[126];

    const int tid = threadIdx.x;
    const int base = blockIdx.x * 128;

    // ---- small epilogue tables ----
    for (int i = tid; i < 504; i += 128) sB1[i] = b1g[i];
    {
        const unsigned long long* w2src = (const unsigned long long*)g_W2p;
        for (int i = tid; i < 504; i += 128) sW2[i] = w2src[i];
    }
    if (tid < 126) sB2[tid] = b2g[tid];

    // ---- stage x: coalesced global -> padded smem rows (float2 granularity) ----
    {
        const float2* xg = (const float2*)(x + (size_t)base * 64);
        #pragma unroll
        for (int k = 0; k < 32; k++) {
            int idx = tid + k * 128;          // 0..4095  (128 rows * 32 float2)
            int row = idx >> 5, c2 = idx & 31;
            float2 v = xg[idx];
            *(float2*)&sXZ[row * XZ_STRIDE + 2 * c2] = v;
        }
    }
    __syncthreads();

    // ---- own x row into registers (32 u64 pairs) ----
    unsigned long long xp[32];
    #pragma unroll
    for (int i = 0; i < 32; i++)
        xp[i] = *(const unsigned long long*)&sXZ[tid * XZ_STRIDE + 2 * i];

    const float mu0 = ipar[0];
    const float al0 = ipar[1];
    float ld = al0;
    {
        float a0, a1; unpack2(xp[0], a0, a1);
        sXZ[tid * XZ_STRIDE + 0] = a0 * exp_fast(al0) + mu0;
    }

    #pragma unroll
    for (int l = 0; l < L_NUM; l++) {
        unsigned long long acc[8];
        #pragma unroll
        for (int j = 0; j < 8; j++) acc[j] = 0ull;

        const int ndp = (l >> 1) + 1;
        #pragma unroll
        for (int dp = 0; dp < ndp; dp++) {
            const int blk = S_blk(l) + dp;       // compile-time after unroll
            ulonglong2 e0 = c_W[blk * 4 + 0];
            ulonglong2 e1 = c_W[blk * 4 + 1];
            ulonglong2 e2 = c_W[blk * 4 + 2];
            ulonglong2 e3 = c_W[blk * 4 + 3];
            unsigned long long xv = xp[dp];
            acc[0] = fma2(xv, e0.x, acc[0]);
            acc[1] = fma2(xv, e0.y, acc[1]);
            acc[2] = fma2(xv, e1.x, acc[2]);
            acc[3] = fma2(xv, e1.y, acc[3]);
            acc[4] = fma2(xv, e2.x, acc[4]);
            acc[5] = fma2(xv, e2.y, acc[5]);
            acc[6] = fma2(xv, e3.x, acc[6]);
            acc[7] = fma2(xv, e3.y, acc[7]);
        }

        // reduce + bias + tanh; layer-2 as packed (mu, alpha) f32x2
        unsigned long long ma;
        {
            float m0 = sB2[2 * l], a0 = sB2[2 * l + 1];
            asm("mov.b64 %0, {%1, %2};" : "=l"(ma) : "f"(m0), "f"(a0));
        }
        #pragma unroll
        for (int j = 0; j < 8; j++) {
            float lo, hi;
            unpack2(acc[j], lo, hi);
            float h = tanh_fast(lo + hi + sB1[l * 8 + j]);
            ma = fma2(dup2(h), sW2[l * 8 + j], ma);
        }
        float mu, al;
        unpack2(ma, mu, al);
        ld += al;

        float xn;
        {
            float lo, hi;
            unpack2(xp[(l + 1) >> 1], lo, hi);
            xn = ((l + 1) & 1) ? hi : lo;
        }
        sXZ[tid * XZ_STRIDE + l + 1] = xn * exp_fast(al) + mu;
    }

    if (has_ld) ld_out[base + tid] = ld;

    __syncthreads();
    // ---- coalesced z writeback ----
    {
        float2* zg = (float2*)(z_out + (size_t)base * 64);
        #pragma unroll
        for (int k = 0; k < 32; k++) {
            int idx = tid + k * 128;
            int row = idx >> 5, c2 = idx & 31;
            float2 v = *(const float2*)&sXZ[row * XZ_STRIDE + 2 * c2];
            zg[idx] = v;
        }
    }
}

extern "C" void kernel_launch(void* const* d_in, const int* in_sizes, int n_in,
                              void* d_out, int out_size) {
    const float* x  = (const float*)d_in[0];
    const float* ip = (const float*)d_in[1];
    const float* W1 = (const float*)d_in[2];
    const float* b1 = (const float*)d_in[3];
    const float* W2 = (const float*)d_in[4];
    const float* b2 = (const float*)d_in[5];

    int B = in_sizes[0] / 64;
    float* z   = (float*)d_out;
    float* ldp = z + (size_t)B * 64;
    int has_ld = (out_size >= B * 64 + B) ? 1 : 0;

    int prep_n = 63 * 32 * 16 + L_NUM * 8;
    prep_kernel<<<(prep_n + 255) / 256, 256>>>(W1, W2);

    // stage the compact table into constant memory (async D2D copy, graph-capturable)
    void* wt_dev = nullptr;
    cudaGetSymbolAddress(&wt_dev, g_Wt);
    cudaMemcpyToSymbolAsync(c_W, wt_dev, WT_FLOATS * sizeof(float), 0,
                            cudaMemcpyDeviceToDevice);

    flow_kernel<<<B / 128, 128>>>(x, ip, b1, b2, z, ldp, has_ld);
}

// round 7
// speedup vs baseline: 1.0713x; 1.0713x over previous
#include <cuda_runtime.h>
#include <cstdint>

#define L_NUM 63

// compact block index: S(l) = number of (layer,dpair) blocks before layer l
__host__ __device__ __forceinline__ constexpr int S_blk(int l) {
    int m = l >> 1;
    return (l & 1) ? (m + 1) * (m + 1) : m * (m + 1);
}
#define NBLK 1024

// staging tables written by prep kernel
__device__ ulonglong2 g_lo[NBLK * 2];   // h0..h3 per block  (32 KB)
__device__ ulonglong2 g_hi[NBLK * 2];   // h4..h7 per block  (32 KB)
__device__ float g_B1[504];
__device__ unsigned long long g_W2p[504];
__device__ float g_B2[126];

// constant-memory copies (separate port from the smem crossbar)
__constant__ ulonglong2 c_Wlo[NBLK * 2];          // 32 KB
__constant__ float c_B1[504];
__constant__ unsigned long long c_W2p[504];
__constant__ float c_B2[126];

// masked / transposed / d-pair-interleaved compact weight tables (split by h half)
__global__ void prep_kernel(const float* __restrict__ W1, const float* __restrict__ W2,
                            const float* __restrict__ b1, const float* __restrict__ b2) {
    int i = blockIdx.x * blockDim.x + threadIdx.x;
    if (i < 63 * 32 * 16) {
        int p  = i & 1;
        int h  = (i >> 1) & 7;
        int dp = (i >> 4) & 31;
        int l  = i >> 9;
        if (dp <= (l >> 1)) {
            int d = 2 * dp + p;
            float v = (d <= l) ? W1[l * 504 + h * 63 + d] : 0.0f;
            int blk = S_blk(l) + dp;
            float* tbl = (h < 4) ? (float*)g_lo : (float*)g_hi;
            int hh = h & 3;
            tbl[blk * 8 + hh * 2 + p] = v;
        }
    } else {
        int j = i - 63 * 32 * 16;
        if (j < 504) {
            int l = j >> 3, h = j & 7;
            float2 w = make_float2(W2[l * 16 + h], W2[l * 16 + 8 + h]);
            g_W2p[j] = *(unsigned long long*)&w;
            g_B1[j] = b1[j];
            if (j < 126) g_B2[j] = b2[j];
        }
    }
}

__device__ __forceinline__ unsigned long long fma2(unsigned long long a,
                                                   unsigned long long b,
                                                   unsigned long long c) {
    unsigned long long d;
    asm("fma.rn.f32x2 %0, %1, %2, %3;" : "=l"(d) : "l"(a), "l"(b), "l"(c));
    return d;
}
__device__ __forceinline__ void unpack2(unsigned long long v, float& lo, float& hi) {
    asm("mov.b64 {%0, %1}, %2;" : "=f"(lo), "=f"(hi) : "l"(v));
}
__device__ __forceinline__ unsigned long long dup2(float f) {
    unsigned long long v;
    asm("mov.b64 %0, {%1, %1};" : "=l"(v) : "f"(f));
    return v;
}
__device__ __forceinline__ float tanh_fast(float a) {
    float y; asm("tanh.approx.f32 %0, %1;" : "=f"(y) : "f"(a)); return y;
}
__device__ __forceinline__ float exp_fast(float a) {
    float y; asm("ex2.approx.f32 %0, %1;" : "=f"(y) : "f"(a * 1.442695041f)); return y;
}

// SMEM: [0, 32KB) hi-half weight table; [32KB, ...) XZ rows 512 x 66 floats
#define OFF_XZ_F 8192           // float index of XZ base (32768 B / 4)
#define XZ_STRIDE 66
#define SMEM_FLOATS (8192 + 512 * 66)

__global__ __launch_bounds__(512, 1)
void flow_kernel(const float* __restrict__ x,
                 const float* __restrict__ ipar,
                 float* __restrict__ z_out,
                 float* __restrict__ ld_out,
                 int has_ld)
{
    extern __shared__ float smem[];
    const int tid = threadIdx.x;
    const int base = blockIdx.x * 512;

    // ---- fill hi-half weight table into smem (32 KB) ----
    {
        const float4* src = (const float4*)g_hi;
        float4* dst = (float4*)smem;
        #pragma unroll
        for (int k = 0; k < 4; k++) dst[tid + k * 512] = src[tid + k * 512];
    }
    // ---- stage x: coalesced global -> padded smem rows ----
    {
        const float2* xg = (const float2*)(x + (size_t)base * 64);
        #pragma unroll
        for (int k = 0; k < 32; k++) {
            int idx = tid + k * 512;            // 0..16383 (512 rows * 32 float2)
            int row = idx >> 5, c2 = idx & 31;
            float2 v = xg[idx];
            *(float2*)&smem[OFF_XZ_F + row * XZ_STRIDE + 2 * c2] = v;
        }
    }
    __syncthreads();

    // ---- own x row into registers (32 u64 pairs) ----
    unsigned long long xp[32];
    #pragma unroll
    for (int i = 0; i < 32; i++)
        xp[i] = *(const unsigned long long*)&smem[OFF_XZ_F + tid * XZ_STRIDE + 2 * i];

    const float mu0 = ipar[0];
    const float al0 = ipar[1];
    float ld = al0;
    {
        float a0, a1; unpack2(xp[0], a0, a1);
        smem[OFF_XZ_F + tid * XZ_STRIDE + 0] = a0 * exp_fast(al0) + mu0;
    }

    const ulonglong2* sW = (const ulonglong2*)smem;   // hi-half table

    #pragma unroll
    for (int l = 0; l < L_NUM; l++) {
        unsigned long long acc[8];
        #pragma unroll
        for (int j = 0; j < 8; j++) acc[j] = 0ull;

        const int ndp = (l >> 1) + 1;
        #pragma unroll
        for (int dp = 0; dp < ndp; dp++) {
            const int blk = S_blk(l) + dp;      // compile-time after unroll
            ulonglong2 e0 = c_Wlo[blk * 2 + 0];   // const port: h0,h1
            ulonglong2 e1 = c_Wlo[blk * 2 + 1];   // const port: h2,h3
            ulonglong2 e2 = sW[blk * 2 + 0];      // smem port:  h4,h5
            ulonglong2 e3 = sW[blk * 2 + 1];      // smem port:  h6,h7
            unsigned long long xv = xp[dp];
            acc[0] = fma2(xv, e0.x, acc[0]);
            acc[1] = fma2(xv, e0.y, acc[1]);
            acc[2] = fma2(xv, e1.x, acc[2]);
            acc[3] = fma2(xv, e1.y, acc[3]);
            acc[4] = fma2(xv, e2.x, acc[4]);
            acc[5] = fma2(xv, e2.y, acc[5]);
            acc[6] = fma2(xv, e3.x, acc[6]);
            acc[7] = fma2(xv, e3.y, acc[7]);
        }

        // reduce + bias + tanh; layer-2 as packed (mu, alpha) f32x2 (const tables)
        unsigned long long ma;
        {
            float m0 = c_B2[2 * l], a0 = c_B2[2 * l + 1];
            asm("mov.b64 %0, {%1, %2};" : "=l"(ma) : "f"(m0), "f"(a0));
        }
        #pragma unroll
        for (int j = 0; j < 8; j++) {
            float lo, hi;
            unpack2(acc[j], lo, hi);
            float h = tanh_fast(lo + hi + c_B1[l * 8 + j]);
            ma = fma2(dup2(h), c_W2p[l * 8 + j], ma);
        }
        float mu, al;
        unpack2(ma, mu, al);
        ld += al;

        float xn;
        {
            float lo, hi;
            unpack2(xp[(l + 1) >> 1], lo, hi);
            xn = ((l + 1) & 1) ? hi : lo;
        }
        smem[OFF_XZ_F + tid * XZ_STRIDE + l + 1] = xn * exp_fast(al) + mu;
    }

    if (has_ld) ld_out[base + tid] = ld;

    __syncthreads();
    // ---- coalesced z writeback ----
    {
        float2* zg = (float2*)(z_out + (size_t)base * 64);
        #pragma unroll
        for (int k = 0; k < 32; k++) {
            int idx = tid + k * 512;
            int row = idx >> 5, c2 = idx & 31;
            float2 v = *(const float2*)&smem[OFF_XZ_F + row * XZ_STRIDE + 2 * c2];
            zg[idx] = v;
        }
    }
}

extern "C" void kernel_launch(void* const* d_in, const int* in_sizes, int n_in,
                              void* d_out, int out_size) {
    const float* x  = (const float*)d_in[0];
    const float* ip = (const float*)d_in[1];
    const float* W1 = (const float*)d_in[2];
    const float* b1 = (const float*)d_in[3];
    const float* W2 = (const float*)d_in[4];
    const float* b2 = (const float*)d_in[5];

    int B = in_sizes[0] / 64;
    float* z   = (float*)d_out;
    float* ldp = z + (size_t)B * 64;
    int has_ld = (out_size >= B * 64 + B) ? 1 : 0;

    int prep_n = 63 * 32 * 16 + 512;
    prep_kernel<<<(prep_n + 255) / 256, 256>>>(W1, W2, b1, b2);

    // stage const tables (async D2D copies; graph-capturable)
    void* p = nullptr;
    cudaGetSymbolAddress(&p, g_lo);
    cudaMemcpyToSymbolAsync(c_Wlo, p, sizeof(g_lo), 0, cudaMemcpyDeviceToDevice);
    cudaGetSymbolAddress(&p, g_B1);
    cudaMemcpyToSymbolAsync(c_B1, p, sizeof(g_B1), 0, cudaMemcpyDeviceToDevice);
    cudaGetSymbolAddress(&p, g_W2p);
    cudaMemcpyToSymbolAsync(c_W2p, p, sizeof(g_W2p), 0, cudaMemcpyDeviceToDevice);
    cudaGetSymbolAddress(&p, g_B2);
    cudaMemcpyToSymbolAsync(c_B2, p, sizeof(g_B2), 0, cudaMemcpyDeviceToDevice);

    size_t smem = (size_t)SMEM_FLOATS * sizeof(float);
    cudaFuncSetAttribute(flow_kernel, cudaFuncAttributeMaxDynamicSharedMemorySize, (int)smem);
    flow_kernel<<<B / 512, 512, smem>>>(x, ip, z, ldp, has_ld);
}